// round 2
// baseline (speedup 1.0000x reference)
#include <cuda_runtime.h>
#include <cstddef>

// GloVe loss — single-kernel version for GB300 (sm_103a).
// Fused: gather + dot + weighted-sq-err + grid reduction + final write,
// using a last-block-done pattern so no separate zero/finalize launches.

static constexpr int EMB            = 300;
static constexpr int NV4            = EMB / 4;      // 75 float4 per row
static constexpr int BATCH_N        = 262144;
static constexpr int THREADS        = 256;
static constexpr int WARPS_PER_BLK  = THREADS / 32; // 8
static constexpr int ROWS_PER_WARP  = 4;
static constexpr int BLOCKS         = BATCH_N / (WARPS_PER_BLK * ROWS_PER_WARP); // 8192

// Zero-initialized at module load; reset back to zero by the last block of
// every launch, so every invocation (correctness run + each graph replay)
// sees identical initial state. Deterministic.
__device__ double       g_acc;
__device__ unsigned int g_done;

__global__ __launch_bounds__(THREADS) void glove_main_kernel(
    const int*   __restrict__ center,
    const int*   __restrict__ outside,
    const float* __restrict__ coocs,
    const float* __restrict__ weighting,
    const float* __restrict__ cemb,
    const float* __restrict__ oemb,
    const float* __restrict__ cbias,
    const float* __restrict__ obias,
    float*       __restrict__ out)
{
    const int lane  = threadIdx.x & 31;
    const int warp  = threadIdx.x >> 5;
    const int gwarp = blockIdx.x * WARPS_PER_BLK + warp;

    float wsum = 0.0f;

    #pragma unroll
    for (int rr = 0; rr < ROWS_PER_WARP; rr += 2) {
        const int row0 = gwarp * ROWS_PER_WARP + rr;
        const int row1 = row0 + 1;

        const int ci0 = __ldg(center  + row0);
        const int oi0 = __ldg(outside + row0);
        const int ci1 = __ldg(center  + row1);
        const int oi1 = __ldg(outside + row1);

        const float4* __restrict__ ca0 = reinterpret_cast<const float4*>(cemb + (size_t)ci0 * EMB);
        const float4* __restrict__ ob0 = reinterpret_cast<const float4*>(oemb + (size_t)oi0 * EMB);
        const float4* __restrict__ ca1 = reinterpret_cast<const float4*>(cemb + (size_t)ci1 * EMB);
        const float4* __restrict__ ob1 = reinterpret_cast<const float4*>(oemb + (size_t)oi1 * EMB);

        // Front-batch all 12 independent LDG.E.128 (2 rows x 2 tables x 3 chunks).
        float4 a00 = __ldg(ca0 + lane);
        float4 b00 = __ldg(ob0 + lane);
        float4 a10 = __ldg(ca1 + lane);
        float4 b10 = __ldg(ob1 + lane);
        float4 a01 = __ldg(ca0 + lane + 32);
        float4 b01 = __ldg(ob0 + lane + 32);
        float4 a11 = __ldg(ca1 + lane + 32);
        float4 b11 = __ldg(ob1 + lane + 32);
        float4 a02 = make_float4(0.f, 0.f, 0.f, 0.f);
        float4 b02 = make_float4(0.f, 0.f, 0.f, 0.f);
        float4 a12 = make_float4(0.f, 0.f, 0.f, 0.f);
        float4 b12 = make_float4(0.f, 0.f, 0.f, 0.f);
        if (lane < NV4 - 64) {   // lanes 0..10 cover float4 indices 64..74
            a02 = __ldg(ca0 + lane + 64);
            b02 = __ldg(ob0 + lane + 64);
            a12 = __ldg(ca1 + lane + 64);
            b12 = __ldg(ob1 + lane + 64);
        }

        float dot0 = a00.x * b00.x + a00.y * b00.y + a00.z * b00.z + a00.w * b00.w;
        dot0      += a01.x * b01.x + a01.y * b01.y + a01.z * b01.z + a01.w * b01.w;
        dot0      += a02.x * b02.x + a02.y * b02.y + a02.z * b02.z + a02.w * b02.w;

        float dot1 = a10.x * b10.x + a10.y * b10.y + a10.z * b10.z + a10.w * b10.w;
        dot1      += a11.x * b11.x + a11.y * b11.y + a11.z * b11.z + a11.w * b11.w;
        dot1      += a12.x * b12.x + a12.y * b12.y + a12.z * b12.z + a12.w * b12.w;

        #pragma unroll
        for (int off = 16; off; off >>= 1) {
            dot0 += __shfl_xor_sync(0xffffffffu, dot0, off);
            dot1 += __shfl_xor_sync(0xffffffffu, dot1, off);
        }

        if (lane == 0) {
            const float err0 = dot0 + __ldg(cbias + ci0) + __ldg(obias + oi0) - __ldg(coocs + row0);
            const float err1 = dot1 + __ldg(cbias + ci1) + __ldg(obias + oi1) - __ldg(coocs + row1);
            wsum += __ldg(weighting + row0) * err0 * err0
                  + __ldg(weighting + row1) * err1 * err1;
        }
    }

    __shared__ float sh[WARPS_PER_BLK];
    if (lane == 0) sh[warp] = wsum;
    __syncthreads();

    if (threadIdx.x == 0) {
        float s = 0.0f;
        #pragma unroll
        for (int i = 0; i < WARPS_PER_BLK; ++i) s += sh[i];
        atomicAdd(&g_acc, (double)s);

        // Last-block-done: the final block writes the result and restores
        // g_acc/g_done to 0 for the next (identical) invocation.
        __threadfence();
        const unsigned t = atomicAdd(&g_done, 1u);
        if (t == (unsigned)(BLOCKS - 1)) {
            const double v = atomicAdd(&g_acc, 0.0);  // coherent read via L2
            out[0] = (float)v;
            g_acc  = 0.0;
            g_done = 0u;
        }
    }
}

extern "C" void kernel_launch(void* const* d_in, const int* in_sizes, int n_in,
                              void* d_out, int out_size) {
    const int*   center    = (const int*)  d_in[0];
    const int*   outside   = (const int*)  d_in[1];
    const float* coocs     = (const float*)d_in[2];
    const float* weighting = (const float*)d_in[3];
    const float* cemb      = (const float*)d_in[4];
    const float* oemb      = (const float*)d_in[5];
    const float* cbias     = (const float*)d_in[6];
    const float* obias     = (const float*)d_in[7];
    float* out = (float*)d_out;

    glove_main_kernel<<<BLOCKS, THREADS>>>(center, outside, coocs, weighting,
                                           cemb, oemb, cbias, obias, out);
}